// round 6
// baseline (speedup 1.0000x reference)
#include <cuda_runtime.h>
#include <math.h>

#define NU 50000
#define NP 50000
#define NEMAX 400000
#define IND 128
#define HID 64
#define NH 4
#define HH 256   // HEADS*HID
#define OUTD 64
#define SCHUNK 4096
#define NCHUNK ((NU + SCHUNK - 1) / SCHUNK)   // 13

// f32x2 packed math (Blackwell sm_10x)
#define FMA_F32X2(d, a, b, c) \
    asm("fma.rn.f32x2 %0, %1, %2, %3;" : "=l"(d) : "l"(a), "l"(b), "l"(c))

#define FMA16(acc, Adrow, Bsrow, tx, ty) do {                                  \
    const ulonglong2* ap_ = (const ulonglong2*)&(Adrow)[(ty) * 16];            \
    ulonglong2 a01_ = ap_[0], a23_ = ap_[1], a45_ = ap_[2], a67_ = ap_[3];     \
    ulonglong2 bv_ = *(const ulonglong2*)&(Bsrow)[(tx) * 4];                   \
    FMA_F32X2(acc[0][0], a01_.x, bv_.x, acc[0][0]);                            \
    FMA_F32X2(acc[0][1], a01_.x, bv_.y, acc[0][1]);                            \
    FMA_F32X2(acc[1][0], a01_.y, bv_.x, acc[1][0]);                            \
    FMA_F32X2(acc[1][1], a01_.y, bv_.y, acc[1][1]);                            \
    FMA_F32X2(acc[2][0], a23_.x, bv_.x, acc[2][0]);                            \
    FMA_F32X2(acc[2][1], a23_.x, bv_.y, acc[2][1]);                            \
    FMA_F32X2(acc[3][0], a23_.y, bv_.x, acc[3][0]);                            \
    FMA_F32X2(acc[3][1], a23_.y, bv_.y, acc[3][1]);                            \
    FMA_F32X2(acc[4][0], a45_.x, bv_.x, acc[4][0]);                            \
    FMA_F32X2(acc[4][1], a45_.x, bv_.y, acc[4][1]);                            \
    FMA_F32X2(acc[5][0], a45_.y, bv_.x, acc[5][0]);                            \
    FMA_F32X2(acc[5][1], a45_.y, bv_.y, acc[5][1]);                            \
    FMA_F32X2(acc[6][0], a67_.x, bv_.x, acc[6][0]);                            \
    FMA_F32X2(acc[6][1], a67_.x, bv_.y, acc[6][1]);                            \
    FMA_F32X2(acc[7][0], a67_.y, bv_.x, acc[7][0]);                            \
    FMA_F32X2(acc[7][1], a67_.y, bv_.y, acc[7][1]);                            \
} while (0)

// ---------------- scratch (static device globals; no allocation) ----------------
__device__ float  g_hu[NU * HID];
__device__ float  g_hp[NP * HID];
__device__ float  g_z[3][NU * HH];       // aggregated per-head features
__device__ float  g_a[6][NU * NH];       // folded attention scalars
__device__ float  g_wf[6][HID * NH];     // folded lin@att^T
__device__ int    g_psrc[3][NEMAX];      // src in CSR slot order
__device__ int    g_cnt3[3][NU];
__device__ int    g_rp3[3][NU + 1];
__device__ int    g_cur3[3][NU];
__device__ int    g_csum[3][NCHUNK];
__device__ int    g_coff[3][NCHUNK];

__device__ __forceinline__ float lrelu(float x) {
    return fmaxf(x, 0.f) + 0.2f * fminf(x, 0.f);
}
__device__ __forceinline__ float elu(float x) {
    return x > 0.f ? x : expm1f(x);
}

// ---------------- fold lin @ att^T into [64,4] per (edge-type, src/dst) ----------------
__global__ void k_fold(const float* __restrict__ l0, const float* __restrict__ l1,
                       const float* __restrict__ l2,
                       const float* __restrict__ a0, const float* __restrict__ a1,
                       const float* __restrict__ a2, const float* __restrict__ a3,
                       const float* __restrict__ a4, const float* __restrict__ a5) {
    int combo = blockIdx.x;  // 0..5
    const float* lin = combo < 2 ? l0 : (combo < 4 ? l1 : l2);
    const float* att = combo == 0 ? a0 : combo == 1 ? a1 : combo == 2 ? a2
                     : combo == 3 ? a3 : combo == 4 ? a4 : a5;
    int t = threadIdx.x;          // 256 threads = 64 cin x 4 heads
    int cin = t >> 2, h = t & 3;
    const float* lr = lin + cin * HH + h * HID;
    const float* ar = att + h * HID;
    float s = 0.f;
#pragma unroll 8
    for (int c = 0; c < HID; ++c) s += lr[c] * ar[c];
    g_wf[combo][cin * NH + h] = s;
}

// ---------------- projection (f32x2): [100000,128]@[128,64] + b -> g_hu / g_hp ----------------
__global__ void __launch_bounds__(256, 3) k_proj(const float* __restrict__ xu,
                                                 const float* __restrict__ xp,
                                                 const float* __restrict__ W,
                                                 const float* __restrict__ b) {
    __shared__ float Ad[32][260];   // duplicated A: [k][2*m]
    __shared__ float Bs[32][68];
    int tid = threadIdx.x;
    int r0 = blockIdx.x * 128;
    int tx = tid & 15, ty = tid >> 4;
    unsigned long long acc[8][2];
#pragma unroll
    for (int i = 0; i < 8; ++i) { acc[i][0] = 0ull; acc[i][1] = 0ull; }

    for (int kk = 0; kk < IND; kk += 32) {
#pragma unroll
        for (int i = 0; i < 4; ++i) {
            int f4 = i * 256 + tid;
            int row = f4 >> 3, kc4 = f4 & 7;
            int gr = r0 + row;
            float4 v = make_float4(0.f, 0.f, 0.f, 0.f);
            if (gr < NU + NP) {
                const float* srcp = gr < NU ? xu + (size_t)gr * IND
                                            : xp + (size_t)(gr - NU) * IND;
                v = *(const float4*)(srcp + kk + kc4 * 4);
            }
            Ad[kc4 * 4 + 0][2 * row] = v.x; Ad[kc4 * 4 + 0][2 * row + 1] = v.x;
            Ad[kc4 * 4 + 1][2 * row] = v.y; Ad[kc4 * 4 + 1][2 * row + 1] = v.y;
            Ad[kc4 * 4 + 2][2 * row] = v.z; Ad[kc4 * 4 + 2][2 * row + 1] = v.z;
            Ad[kc4 * 4 + 3][2 * row] = v.w; Ad[kc4 * 4 + 3][2 * row + 1] = v.w;
        }
#pragma unroll
        for (int i = 0; i < 2; ++i) {
            int f4 = i * 256 + tid;
            int k = f4 >> 4, c4 = f4 & 15;
            *(float4*)&Bs[k][c4 * 4] = *(const float4*)(W + (kk + k) * 64 + c4 * 4);
        }
        __syncthreads();
#pragma unroll
        for (int k = 0; k < 32; ++k) FMA16(acc, Ad[k], Bs[k], tx, ty);
        __syncthreads();
    }
    float4 bb = *(const float4*)(b + tx * 4);
#pragma unroll
    for (int i = 0; i < 8; ++i) {
        int gr = r0 + ty * 8 + i;
        if (gr >= NU + NP) continue;
        float2 p0 = *(float2*)&acc[i][0];
        float2 p1 = *(float2*)&acc[i][1];
        float4 o = make_float4(p0.x + bb.x, p0.y + bb.y, p1.x + bb.z, p1.y + bb.w);
        float* dst = gr < NU ? g_hu + (size_t)gr * HID
                             : g_hp + (size_t)(gr - NU) * HID;
        *(float4*)(dst + tx * 4) = o;
    }
}

// ---------------- attention scalars, H read once per node ----------------
__global__ void k_att2() {
    int part = blockIdx.y;
    __shared__ float wf[4][HID * NH];
    int nz = part ? 2 : 4;
    int zsU[4] = {0, 1, 3, 4};
    int zsP[2] = {2, 5};
#pragma unroll
    for (int zi = 0; zi < 4; ++zi) {
        if (zi < nz) {
            int z = part ? zsP[zi] : zsU[zi];
            wf[zi][threadIdx.x] = g_wf[z][threadIdx.x];
        }
    }
    __syncthreads();
    int node = blockIdx.x * 256 + threadIdx.x;
    if (node >= NU) return;
    const float* hr = (part ? g_hp : g_hu) + (size_t)node * HID;
    float acc[4][4] = {};
#pragma unroll
    for (int c = 0; c < HID; c += 4) {
        float4 h4 = *(const float4*)(hr + c);
#pragma unroll
        for (int zi = 0; zi < 4; ++zi) {
            if (zi >= nz) break;
#pragma unroll
            for (int hh = 0; hh < 4; ++hh) {
                acc[zi][hh] += h4.x * wf[zi][(c + 0) * 4 + hh]
                             + h4.y * wf[zi][(c + 1) * 4 + hh]
                             + h4.z * wf[zi][(c + 2) * 4 + hh]
                             + h4.w * wf[zi][(c + 3) * 4 + hh];
            }
        }
    }
#pragma unroll
    for (int zi = 0; zi < 4; ++zi) {
        if (zi >= nz) break;
        int z = part ? zsP[zi] : zsU[zi];
        *(float4*)&g_a[z][node * 4] =
            make_float4(acc[zi][0], acc[zi][1], acc[zi][2], acc[zi][3]);
    }
}

// ---------------- batched CSR build ----------------
__global__ void k_zero3() {
    int i = blockIdx.x * 256 + threadIdx.x;
    if (i < 3 * NU) ((int*)g_cnt3)[i] = 0;
}
__global__ void k_hist3(const int* __restrict__ d0, const int* __restrict__ d1,
                        const int* __restrict__ d2, int E) {
    int t = blockIdx.y;
    const int* dst = t == 0 ? d0 : (t == 1 ? d1 : d2);
    int e = blockIdx.x * 256 + threadIdx.x;
    if (e < E) atomicAdd(&g_cnt3[t][dst[e]], 1);
}
__global__ void __launch_bounds__(1024) k_scan_a() {
    int t = blockIdx.y, chunk = blockIdx.x;
    __shared__ int warpsum[32];
    int tid = threadIdx.x;
    int lane = tid & 31, wid = tid >> 5;
    int idx0 = chunk * SCHUNK + tid * 4;
    int v[4];
    int s = 0;
#pragma unroll
    for (int q = 0; q < 4; ++q) {
        v[q] = (idx0 + q < NU) ? g_cnt3[t][idx0 + q] : 0;
        s += v[q];
    }
    int x = s;
#pragma unroll
    for (int o = 1; o < 32; o <<= 1) {
        int y = __shfl_up_sync(0xffffffffu, x, o);
        if (lane >= o) x += y;
    }
    if (lane == 31) warpsum[wid] = x;
    __syncthreads();
    if (wid == 0) {
        int w = warpsum[lane];
#pragma unroll
        for (int o = 1; o < 32; o <<= 1) {
            int y = __shfl_up_sync(0xffffffffu, w, o);
            if (lane >= o) w += y;
        }
        warpsum[lane] = w;
    }
    __syncthreads();
    int wprev = wid ? warpsum[wid - 1] : 0;
    int excl = wprev + (x - s);
#pragma unroll
    for (int q = 0; q < 4; ++q) {
        if (idx0 + q < NU) g_rp3[t][idx0 + q] = excl;
        excl += v[q];
    }
    if (tid == 0) g_csum[t][chunk] = warpsum[31];
}
__global__ void k_scan_b() {
    int w = threadIdx.x >> 5;
    int lane = threadIdx.x & 31;
    if (w >= 3) return;
    int val = lane < NCHUNK ? g_csum[w][lane] : 0;
    int x = val;
#pragma unroll
    for (int o = 1; o < 32; o <<= 1) {
        int y = __shfl_up_sync(0xffffffffu, x, o);
        if (lane >= o) x += y;
    }
    if (lane < NCHUNK) g_coff[w][lane] = x - val;
    if (lane == 31) g_rp3[w][NU] = x;
}
__global__ void __launch_bounds__(1024) k_scan_c() {
    int t = blockIdx.y, chunk = blockIdx.x;
    int off = g_coff[t][chunk];
    int idx0 = chunk * SCHUNK + threadIdx.x * 4;
#pragma unroll
    for (int q = 0; q < 4; ++q) {
        int i = idx0 + q;
        if (i < NU) {
            int r = g_rp3[t][i] + off;
            g_rp3[t][i] = r;
            g_cur3[t][i] = r;
        }
    }
}

// ---------------- scatter src into CSR slots ----------------
__global__ void k_scat(const int* __restrict__ s0, const int* __restrict__ d0,
                       const int* __restrict__ s1, const int* __restrict__ d1,
                       const int* __restrict__ s2, const int* __restrict__ d2,
                       int E) {
    int t = blockIdx.y;
    const int* src = t == 0 ? s0 : (t == 1 ? s1 : s2);
    const int* dst = t == 0 ? d0 : (t == 1 ? d1 : d2);
    int e = blockIdx.x * 256 + threadIdx.x;
    if (e >= E) return;
    int p = atomicAdd(&g_cur3[t][dst[e]], 1);
    g_psrc[t][p] = src[e];
}

// ---------------- warp-per-dst: logits + softmax + HID-space aggregation ----------------
__global__ void __launch_bounds__(256) k_gat4() {
    int t = blockIdx.y;
    int d = (blockIdx.x * 256 + threadIdx.x) >> 5;
    int lane = threadIdx.x & 31;
    if (d >= NU) return;
    int beg = g_rp3[t][d], end = g_rp3[t][d + 1];
    int deg = end - beg;
    const float* hsrc = (t == 1) ? g_hp : g_hu;
    const int* psrc = g_psrc[t];
    const float* aS = g_a[2 * t];
    float4 ad = *(const float4*)&g_a[2 * t + 1][d * 4];
    int c0 = lane * 2;
    float* zp = &g_z[t][(size_t)d * HH];

    if (deg == 0) {
#pragma unroll
        for (int h = 0; h < 4; ++h)
            *(float2*)&zp[h * HID + c0] = make_float2(0.f, 0.f);
        return;
    }

    float acc[4][2] = {};

    if (deg <= 32) {
        bool valid = lane < deg;
        int sj = valid ? psrc[beg + lane] : 0;
        float4 ev = make_float4(-INFINITY, -INFINITY, -INFINITY, -INFINITY);
        if (valid) {
            float4 s4 = *(const float4*)&aS[sj * 4];
            ev = make_float4(lrelu(s4.x + ad.x), lrelu(s4.y + ad.y),
                             lrelu(s4.z + ad.z), lrelu(s4.w + ad.w));
        }
        float m0 = ev.x, m1 = ev.y, m2 = ev.z, m3 = ev.w;
#pragma unroll
        for (int o = 16; o; o >>= 1) {
            m0 = fmaxf(m0, __shfl_xor_sync(0xffffffffu, m0, o));
            m1 = fmaxf(m1, __shfl_xor_sync(0xffffffffu, m1, o));
            m2 = fmaxf(m2, __shfl_xor_sync(0xffffffffu, m2, o));
            m3 = fmaxf(m3, __shfl_xor_sync(0xffffffffu, m3, o));
        }
        float e0 = valid ? __expf(ev.x - m0) : 0.f;
        float e1 = valid ? __expf(ev.y - m1) : 0.f;
        float e2 = valid ? __expf(ev.z - m2) : 0.f;
        float e3 = valid ? __expf(ev.w - m3) : 0.f;
        float s0 = e0, s1 = e1, s2 = e2, s3 = e3;
#pragma unroll
        for (int o = 16; o; o >>= 1) {
            s0 += __shfl_xor_sync(0xffffffffu, s0, o);
            s1 += __shfl_xor_sync(0xffffffffu, s1, o);
            s2 += __shfl_xor_sync(0xffffffffu, s2, o);
            s3 += __shfl_xor_sync(0xffffffffu, s3, o);
        }
        float ax = e0 / (s0 + 1e-16f);
        float ay = e1 / (s1 + 1e-16f);
        float az = e2 / (s2 + 1e-16f);
        float aw = e3 / (s3 + 1e-16f);
        for (int k = 0; k < deg; ++k) {
            int sr  = __shfl_sync(0xffffffffu, sj, k);
            float bx = __shfl_sync(0xffffffffu, ax, k);
            float by = __shfl_sync(0xffffffffu, ay, k);
            float bz = __shfl_sync(0xffffffffu, az, k);
            float bw = __shfl_sync(0xffffffffu, aw, k);
            float2 v = *(const float2*)&hsrc[(size_t)sr * HID + c0];
            acc[0][0] += bx * v.x; acc[0][1] += bx * v.y;
            acc[1][0] += by * v.x; acc[1][1] += by * v.y;
            acc[2][0] += bz * v.x; acc[2][1] += bz * v.y;
            acc[3][0] += bw * v.x; acc[3][1] += bw * v.y;
        }
    } else {
        float m0 = -INFINITY, m1 = -INFINITY, m2 = -INFINITY, m3 = -INFINITY;
        for (int j = beg + lane; j < end; j += 32) {
            float4 s4 = *(const float4*)&aS[psrc[j] * 4];
            m0 = fmaxf(m0, lrelu(s4.x + ad.x));
            m1 = fmaxf(m1, lrelu(s4.y + ad.y));
            m2 = fmaxf(m2, lrelu(s4.z + ad.z));
            m3 = fmaxf(m3, lrelu(s4.w + ad.w));
        }
#pragma unroll
        for (int o = 16; o; o >>= 1) {
            m0 = fmaxf(m0, __shfl_xor_sync(0xffffffffu, m0, o));
            m1 = fmaxf(m1, __shfl_xor_sync(0xffffffffu, m1, o));
            m2 = fmaxf(m2, __shfl_xor_sync(0xffffffffu, m2, o));
            m3 = fmaxf(m3, __shfl_xor_sync(0xffffffffu, m3, o));
        }
        float s0 = 0.f, s1 = 0.f, s2 = 0.f, s3 = 0.f;
        for (int j = beg + lane; j < end; j += 32) {
            float4 s4 = *(const float4*)&aS[psrc[j] * 4];
            s0 += __expf(lrelu(s4.x + ad.x) - m0);
            s1 += __expf(lrelu(s4.y + ad.y) - m1);
            s2 += __expf(lrelu(s4.z + ad.z) - m2);
            s3 += __expf(lrelu(s4.w + ad.w) - m3);
        }
#pragma unroll
        for (int o = 16; o; o >>= 1) {
            s0 += __shfl_xor_sync(0xffffffffu, s0, o);
            s1 += __shfl_xor_sync(0xffffffffu, s1, o);
            s2 += __shfl_xor_sync(0xffffffffu, s2, o);
            s3 += __shfl_xor_sync(0xffffffffu, s3, o);
        }
        float i0 = 1.f / (s0 + 1e-16f), i1 = 1.f / (s1 + 1e-16f);
        float i2 = 1.f / (s2 + 1e-16f), i3 = 1.f / (s3 + 1e-16f);
        for (int base = beg; base < end; base += 32) {
            int j = base + lane;
            float ax = 0.f, ay = 0.f, az = 0.f, aw = 0.f;
            int sj = 0;
            if (j < end) {
                sj = psrc[j];
                float4 s4 = *(const float4*)&aS[sj * 4];
                ax = __expf(lrelu(s4.x + ad.x) - m0) * i0;
                ay = __expf(lrelu(s4.y + ad.y) - m1) * i1;
                az = __expf(lrelu(s4.z + ad.z) - m2) * i2;
                aw = __expf(lrelu(s4.w + ad.w) - m3) * i3;
            }
            int cnt = min(32, end - base);
            for (int k = 0; k < cnt; ++k) {
                int sr  = __shfl_sync(0xffffffffu, sj, k);
                float bx = __shfl_sync(0xffffffffu, ax, k);
                float by = __shfl_sync(0xffffffffu, ay, k);
                float bz = __shfl_sync(0xffffffffu, az, k);
                float bw = __shfl_sync(0xffffffffu, aw, k);
                float2 v = *(const float2*)&hsrc[(size_t)sr * HID + c0];
                acc[0][0] += bx * v.x; acc[0][1] += bx * v.y;
                acc[1][0] += by * v.x; acc[1][1] += by * v.y;
                acc[2][0] += bz * v.x; acc[2][1] += bz * v.y;
                acc[3][0] += bw * v.x; acc[3][1] += bw * v.y;
            }
        }
    }
#pragma unroll
    for (int hh = 0; hh < 4; ++hh)
        *(float2*)&zp[hh * HID + c0] = make_float2(acc[hh][0], acc[hh][1]);
}

// ---------------- post path: elu(z2@lin2 + bias) -> dout post region ----------------
__global__ void __launch_bounds__(256, 3) k_hpost(const float* __restrict__ l2,
                                                  const float* __restrict__ b2,
                                                  float* __restrict__ dout) {
    __shared__ float Ad[32][260];
    __shared__ float Bs[32][68];
    int h = blockIdx.y;
    int tid = threadIdx.x;
    int r0 = blockIdx.x * 128;
    int tx = tid & 15, ty = tid >> 4;

    unsigned long long acc[8][2];
#pragma unroll
    for (int i = 0; i < 8; ++i) { acc[i][0] = 0ull; acc[i][1] = 0ull; }

    const float* A = g_z[2];
    for (int kk = 0; kk < HID; kk += 32) {
#pragma unroll
        for (int i = 0; i < 4; ++i) {
            int f4 = i * 256 + tid;
            int row = f4 >> 3, kc4 = f4 & 7;
            int gr = r0 + row;
            float4 v = make_float4(0.f, 0.f, 0.f, 0.f);
            if (gr < NU)
                v = *(const float4*)(A + (size_t)gr * HH + h * HID + kk + kc4 * 4);
            Ad[kc4 * 4 + 0][2 * row] = v.x; Ad[kc4 * 4 + 0][2 * row + 1] = v.x;
            Ad[kc4 * 4 + 1][2 * row] = v.y; Ad[kc4 * 4 + 1][2 * row + 1] = v.y;
            Ad[kc4 * 4 + 2][2 * row] = v.z; Ad[kc4 * 4 + 2][2 * row + 1] = v.z;
            Ad[kc4 * 4 + 3][2 * row] = v.w; Ad[kc4 * 4 + 3][2 * row + 1] = v.w;
        }
#pragma unroll
        for (int i = 0; i < 2; ++i) {
            int f4 = i * 256 + tid;
            int k = f4 >> 4, c4 = f4 & 15;
            *(float4*)&Bs[k][c4 * 4] =
                *(const float4*)(l2 + (size_t)(kk + k) * HH + h * HID + c4 * 4);
        }
        __syncthreads();
#pragma unroll
        for (int k = 0; k < 32; ++k) FMA16(acc, Ad[k], Bs[k], tx, ty);
        __syncthreads();
    }
    float4 bb = *(const float4*)(b2 + h * HID + tx * 4);
#pragma unroll
    for (int i = 0; i < 8; ++i) {
        int gr = r0 + ty * 8 + i;
        if (gr >= NU) continue;
        float2 p0 = *(float2*)&acc[i][0];
        float2 p1 = *(float2*)&acc[i][1];
        float4 o = make_float4(elu(p0.x + bb.x), elu(p0.y + bb.y),
                               elu(p1.x + bb.z), elu(p1.y + bb.w));
        *(float4*)(dout + (size_t)NU * OUTD + (size_t)gr * HH + h * HID + tx * 4) = o;
    }
}

// ---------------- fused user path: per-head conv GEMM + ELU -> staged smem -> @W_out ----------------
__global__ void __launch_bounds__(256, 2) k_hgout(const float* __restrict__ l0,
                                                  const float* __restrict__ l1,
                                                  const float* __restrict__ b0,
                                                  const float* __restrict__ b1,
                                                  const float* __restrict__ W,
                                                  const float* __restrict__ bo,
                                                  float* __restrict__ dout) {
    __shared__ float Ad[32][260];
    __shared__ float Bs[32][68];
    int tid = threadIdx.x;
    int r0 = blockIdx.x * 128;
    int tx = tid & 15, ty = tid >> 4;

    unsigned long long goacc[8][2];   // second-GEMM accumulators (persist over heads)
#pragma unroll
    for (int i = 0; i < 8; ++i) { goacc[i][0] = 0ull; goacc[i][1] = 0ull; }

    for (int h = 0; h < NH; ++h) {
        unsigned long long acc[8][2];
#pragma unroll
        for (int i = 0; i < 8; ++i) { acc[i][0] = 0ull; acc[i][1] = 0ull; }

        // --- conv GEMM for this head: z0@lin0 + z1@lin1, K = 2*64 ---
#pragma unroll
        for (int tt = 0; tt < 2; ++tt) {
            const float* A = g_z[tt];
            const float* lin = tt == 0 ? l0 : l1;
            for (int kk = 0; kk < HID; kk += 32) {
#pragma unroll
                for (int i = 0; i < 4; ++i) {
                    int f4 = i * 256 + tid;
                    int row = f4 >> 3, kc4 = f4 & 7;
                    int gr = r0 + row;
                    float4 v = make_float4(0.f, 0.f, 0.f, 0.f);
                    if (gr < NU)
                        v = *(const float4*)(A + (size_t)gr * HH + h * HID + kk + kc4 * 4);
                    Ad[kc4 * 4 + 0][2 * row] = v.x; Ad[kc4 * 4 + 0][2 * row + 1] = v.x;
                    Ad[kc4 * 4 + 1][2 * row] = v.y; Ad[kc4 * 4 + 1][2 * row + 1] = v.y;
                    Ad[kc4 * 4 + 2][2 * row] = v.z; Ad[kc4 * 4 + 2][2 * row + 1] = v.z;
                    Ad[kc4 * 4 + 3][2 * row] = v.w; Ad[kc4 * 4 + 3][2 * row + 1] = v.w;
                }
#pragma unroll
                for (int i = 0; i < 2; ++i) {
                    int f4 = i * 256 + tid;
                    int k = f4 >> 4, c4 = f4 & 15;
                    *(float4*)&Bs[k][c4 * 4] =
                        *(const float4*)(lin + (size_t)(kk + k) * HH + h * HID + c4 * 4);
                }
                __syncthreads();
#pragma unroll
                for (int k = 0; k < 32; ++k) FMA16(acc, Ad[k], Bs[k], tx, ty);
                __syncthreads();
            }
        }

        // --- bias + ELU into cv regs ---
        float4 x1 = *(const float4*)(b0 + h * HID + tx * 4);
        float4 x2 = *(const float4*)(b1 + h * HID + tx * 4);
        float bbx = x1.x + x2.x, bby = x1.y + x2.y, bbz = x1.z + x2.z, bbw = x1.w + x2.w;
        float cv[8][4];
#pragma unroll
        for (int i = 0; i < 8; ++i) {
            float2 p0 = *(float2*)&acc[i][0];
            float2 p1 = *(float2*)&acc[i][1];
            cv[i][0] = elu(p0.x + bbx);
            cv[i][1] = elu(p0.y + bby);
            cv[i][2] = elu(p1.x + bbz);
            cv[i][3] = elu(p1.y + bbw);
        }

        // --- second GEMM: stage this head's 64 channels in two 32-k halves ---
#pragma unroll
        for (int half = 0; half < 2; ++half) {
            __syncthreads();   // protect Ad/Bs reuse
            if ((tx >> 3) == half) {
                int kc = (tx & 7) * 4;   // channel-in-half base 0..28
#pragma unroll
                for (int i = 0; i < 8; ++i) {
                    int row2 = 2 * (ty * 8 + i);
#pragma unroll
                    for (int j = 0; j < 4; ++j) {
                        Ad[kc + j][row2] = cv[i][j];
                        Ad[kc + j][row2 + 1] = cv[i][j];
                    }
                }
            }
            // B tile: W_out rows [h*64 + half*32, +32), cols 0..63
#pragma unroll
            for (int i = 0; i < 2; ++i) {
                int f4 = i * 256 + tid;
                int k = f4 >> 4, c4 = f4 & 15;
                *(float4*)&Bs[k][c4 * 4] =
                    *(const float4*)(W + (size_t)(h * HID + half * 32 + k) * OUTD + c4 * 4);
            }
            __syncthreads();
#pragma unroll
            for (int k = 0; k < 32; ++k) FMA16(goacc, Ad[k], Bs[k], tx, ty);
        }
        __syncthreads();
    }

    float4 bb = *(const float4*)(bo + tx * 4);
#pragma unroll
    for (int i = 0; i < 8; ++i) {
        int gr = r0 + ty * 8 + i;
        if (gr >= NU) continue;
        float2 p0 = *(float2*)&goacc[i][0];
        float2 p1 = *(float2*)&goacc[i][1];
        *(float4*)(dout + (size_t)gr * OUTD + tx * 4) =
            make_float4(p0.x + bb.x, p0.y + bb.y, p1.x + bb.z, p1.y + bb.w);
    }
}

// ---------------- launch ----------------
extern "C" void kernel_launch(void* const* d_in, const int* in_sizes, int n_in,
                              void* d_out, int out_size) {
    const float* x_user     = (const float*)d_in[0];
    const float* x_post     = (const float*)d_in[1];
    const int*   src_u2u    = (const int*)d_in[2];
    const int*   dst_u2u    = (const int*)d_in[3];
    const int*   src_p2u    = (const int*)d_in[4];
    const int*   dst_p2u    = (const int*)d_in[5];
    const int*   src_u2p    = (const int*)d_in[6];
    const int*   dst_u2p    = (const int*)d_in[7];
    const float* W_proj     = (const float*)d_in[8];
    const float* b_proj     = (const float*)d_in[9];
    const float* lin_u2u    = (const float*)d_in[10];
    const float* att_s_u2u  = (const float*)d_in[11];
    const float* att_d_u2u  = (const float*)d_in[12];
    const float* bias_u2u   = (const float*)d_in[13];
    const float* lin_p2u    = (const float*)d_in[14];
    const float* att_s_p2u  = (const float*)d_in[15];
    const float* att_d_p2u  = (const float*)d_in[16];
    const float* bias_p2u   = (const float*)d_in[17];
    const float* lin_u2p    = (const float*)d_in[18];
    const float* att_s_u2p  = (const float*)d_in[19];
    const float* att_d_u2p  = (const float*)d_in[20];
    const float* bias_u2p   = (const float*)d_in[21];
    const float* W_out      = (const float*)d_in[22];
    const float* b_out      = (const float*)d_in[23];
    float* out = (float*)d_out;
    int E = in_sizes[2];
    int gE = (E + 255) / 256;

    // ncu -s 5 lands on stream launch index 3 -> place k_proj there
    k_fold<<<6, 256>>>(lin_u2u, lin_p2u, lin_u2p,                           // 0
                       att_s_u2u, att_d_u2u, att_s_p2u, att_d_p2u, att_s_u2p, att_d_u2p);
    k_zero3<<<(3 * NU + 255) / 256, 256>>>();                               // 1
    k_hist3<<<dim3(gE, 3), 256>>>(dst_u2u, dst_p2u, dst_u2p, E);            // 2
    k_proj<<<(NU + NP + 127) / 128, 256>>>(x_user, x_post, W_proj, b_proj); // 3 (profiled)
    k_scan_a<<<dim3(NCHUNK, 3), 1024>>>();                                  // 4
    k_scan_b<<<1, 96>>>();                                                  // 5
    k_scan_c<<<dim3(NCHUNK, 3), 1024>>>();                                  // 6
    k_att2<<<dim3((NU + 255) / 256, 2), 256>>>();                           // 7
    k_scat<<<dim3(gE, 3), 256>>>(src_u2u, dst_u2u, src_p2u, dst_p2u,        // 8
                                 src_u2p, dst_u2p, E);
    k_gat4<<<dim3((NU * 32 + 255) / 256, 3), 256>>>();                      // 9
    k_hpost<<<dim3((NU + 127) / 128, NH), 256>>>(lin_u2p, bias_u2p, out);   // 10
    k_hgout<<<(NU + 127) / 128, 256>>>(lin_u2u, lin_p2u, bias_u2u, bias_p2u, // 11
                                       W_out, b_out, out);
}

// round 7
// speedup vs baseline: 1.0303x; 1.0303x over previous
#include <cuda_runtime.h>
#include <math.h>

#define NU 50000
#define NP 50000
#define NEMAX 400000
#define IND 128
#define HID 64
#define NH 4
#define HH 256   // HEADS*HID
#define OUTD 64
#define SCHUNK 4096
#define NCHUNK ((NU + SCHUNK - 1) / SCHUNK)   // 13

// f32x2 packed math (Blackwell sm_10x)
#define FMA_F32X2(d, a, b, c) \
    asm("fma.rn.f32x2 %0, %1, %2, %3;" : "=l"(d) : "l"(a), "l"(b), "l"(c))

// 16x4 microtile rank-1 update: 8 row-pairs (natural A) x 4 cols (duplicated B)
#define FMA32(acc, Asrow, Bdrow, tx, ty) do {                                  \
    const ulonglong2* ap_ = (const ulonglong2*)&(Asrow)[(ty) * 16];            \
    ulonglong2 a01_ = ap_[0], a23_ = ap_[1], a45_ = ap_[2], a67_ = ap_[3];     \
    const ulonglong2* bp_ = (const ulonglong2*)&(Bdrow)[(tx) * 8];             \
    ulonglong2 b01_ = bp_[0], b23_ = bp_[1];                                   \
    FMA_F32X2(acc[0][0], a01_.x, b01_.x, acc[0][0]);                           \
    FMA_F32X2(acc[0][1], a01_.x, b01_.y, acc[0][1]);                           \
    FMA_F32X2(acc[0][2], a01_.x, b23_.x, acc[0][2]);                           \
    FMA_F32X2(acc[0][3], a01_.x, b23_.y, acc[0][3]);                           \
    FMA_F32X2(acc[1][0], a01_.y, b01_.x, acc[1][0]);                           \
    FMA_F32X2(acc[1][1], a01_.y, b01_.y, acc[1][1]);                           \
    FMA_F32X2(acc[1][2], a01_.y, b23_.x, acc[1][2]);                           \
    FMA_F32X2(acc[1][3], a01_.y, b23_.y, acc[1][3]);                           \
    FMA_F32X2(acc[2][0], a23_.x, b01_.x, acc[2][0]);                           \
    FMA_F32X2(acc[2][1], a23_.x, b01_.y, acc[2][1]);                           \
    FMA_F32X2(acc[2][2], a23_.x, b23_.x, acc[2][2]);                           \
    FMA_F32X2(acc[2][3], a23_.x, b23_.y, acc[2][3]);                           \
    FMA_F32X2(acc[3][0], a23_.y, b01_.x, acc[3][0]);                           \
    FMA_F32X2(acc[3][1], a23_.y, b01_.y, acc[3][1]);                           \
    FMA_F32X2(acc[3][2], a23_.y, b23_.x, acc[3][2]);                           \
    FMA_F32X2(acc[3][3], a23_.y, b23_.y, acc[3][3]);                           \
    FMA_F32X2(acc[4][0], a45_.x, b01_.x, acc[4][0]);                           \
    FMA_F32X2(acc[4][1], a45_.x, b01_.y, acc[4][1]);                           \
    FMA_F32X2(acc[4][2], a45_.x, b23_.x, acc[4][2]);                           \
    FMA_F32X2(acc[4][3], a45_.x, b23_.y, acc[4][3]);                           \
    FMA_F32X2(acc[5][0], a45_.y, b01_.x, acc[5][0]);                           \
    FMA_F32X2(acc[5][1], a45_.y, b01_.y, acc[5][1]);                           \
    FMA_F32X2(acc[5][2], a45_.y, b23_.x, acc[5][2]);                           \
    FMA_F32X2(acc[5][3], a45_.y, b23_.y, acc[5][3]);                           \
    FMA_F32X2(acc[6][0], a67_.x, b01_.x, acc[6][0]);                           \
    FMA_F32X2(acc[6][1], a67_.x, b01_.y, acc[6][1]);                           \
    FMA_F32X2(acc[6][2], a67_.x, b23_.x, acc[6][2]);                           \
    FMA_F32X2(acc[6][3], a67_.x, b23_.y, acc[6][3]);                           \
    FMA_F32X2(acc[7][0], a67_.y, b01_.x, acc[7][0]);                           \
    FMA_F32X2(acc[7][1], a67_.y, b01_.y, acc[7][1]);                           \
    FMA_F32X2(acc[7][2], a67_.y, b23_.x, acc[7][2]);                           \
    FMA_F32X2(acc[7][3], a67_.y, b23_.y, acc[7][3]);                           \
} while (0)

// A tile: 256 rows x 32 k, natural [k][m] layout (2048 float4, 8/thread)
#define LOAD_A256(As, Aptr, lda, coff, r0, kk, Mlim) do {                      \
    _Pragma("unroll")                                                          \
    for (int i_ = 0; i_ < 8; ++i_) {                                           \
        int f4_ = i_ * 256 + tid;                                              \
        int row_ = f4_ >> 3, kc4_ = f4_ & 7;                                   \
        int gr_ = (r0) + row_;                                                 \
        float4 v_ = make_float4(0.f, 0.f, 0.f, 0.f);                           \
        if (gr_ < (Mlim))                                                      \
            v_ = *(const float4*)((Aptr) + (size_t)gr_ * (lda) + (coff) + (kk) + kc4_ * 4); \
        (As)[kc4_ * 4 + 0][row_] = v_.x;                                       \
        (As)[kc4_ * 4 + 1][row_] = v_.y;                                       \
        (As)[kc4_ * 4 + 2][row_] = v_.z;                                       \
        (As)[kc4_ * 4 + 3][row_] = v_.w;                                       \
    }                                                                          \
} while (0)

// B tile: 32 k x 64 cols, duplicated (512 float4 source, 2/thread)
#define LOAD_BDUP(Bd, Bptr, ldb, coff, kk) do {                                \
    _Pragma("unroll")                                                          \
    for (int i_ = 0; i_ < 2; ++i_) {                                           \
        int f4_ = i_ * 256 + tid;                                              \
        int k_ = f4_ >> 4, c4_ = f4_ & 15;                                     \
        float4 w_ = *(const float4*)((Bptr) + (size_t)((kk) + k_) * (ldb) + (coff) + c4_ * 4); \
        (Bd)[k_][c4_ * 8 + 0] = w_.x; (Bd)[k_][c4_ * 8 + 1] = w_.x;            \
        (Bd)[k_][c4_ * 8 + 2] = w_.y; (Bd)[k_][c4_ * 8 + 3] = w_.y;            \
        (Bd)[k_][c4_ * 8 + 4] = w_.z; (Bd)[k_][c4_ * 8 + 5] = w_.z;            \
        (Bd)[k_][c4_ * 8 + 6] = w_.w; (Bd)[k_][c4_ * 8 + 7] = w_.w;            \
    }                                                                          \
} while (0)

// ---------------- scratch (static device globals; no allocation) ----------------
__device__ float  g_hu[NU * HID];
__device__ float  g_hp[NP * HID];
__device__ float  g_z[3][NU * HH];       // aggregated per-head features
__device__ float  g_a[6][NU * NH];       // folded attention scalars
__device__ float  g_wf[6][HID * NH];     // folded lin@att^T
__device__ int    g_psrc[3][NEMAX];      // src in CSR slot order
__device__ int    g_cnt3[3][NU];
__device__ int    g_rp3[3][NU + 1];
__device__ int    g_cur3[3][NU];
__device__ int    g_csum[3][NCHUNK];
__device__ int    g_coff[3][NCHUNK];
__device__ float  g_outU[NU * HH];       // elu(conv_u2u + conv_p2u + biases)

__device__ __forceinline__ float lrelu(float x) {
    return fmaxf(x, 0.f) + 0.2f * fminf(x, 0.f);
}
__device__ __forceinline__ float elu(float x) {
    return x > 0.f ? x : expm1f(x);
}

// ---------------- fold lin @ att^T into [64,4] per (edge-type, src/dst) ----------------
__global__ void k_fold(const float* __restrict__ l0, const float* __restrict__ l1,
                       const float* __restrict__ l2,
                       const float* __restrict__ a0, const float* __restrict__ a1,
                       const float* __restrict__ a2, const float* __restrict__ a3,
                       const float* __restrict__ a4, const float* __restrict__ a5) {
    int combo = blockIdx.x;  // 0..5
    const float* lin = combo < 2 ? l0 : (combo < 4 ? l1 : l2);
    const float* att = combo == 0 ? a0 : combo == 1 ? a1 : combo == 2 ? a2
                     : combo == 3 ? a3 : combo == 4 ? a4 : a5;
    int t = threadIdx.x;          // 256 threads = 64 cin x 4 heads
    int cin = t >> 2, h = t & 3;
    const float* lr = lin + cin * HH + h * HID;
    const float* ar = att + h * HID;
    float s = 0.f;
#pragma unroll 8
    for (int c = 0; c < HID; ++c) s += lr[c] * ar[c];
    g_wf[combo][cin * NH + h] = s;
}

// ---------------- projection: [100000,128]@[128,64] + b -> g_hu / g_hp ----------------
__global__ void __launch_bounds__(256, 2) k_proj(const float* __restrict__ xu,
                                                 const float* __restrict__ xp,
                                                 const float* __restrict__ W,
                                                 const float* __restrict__ b) {
    __shared__ float As[32][264];   // natural [k][m], 256 rows
    __shared__ float Bd[32][136];   // duplicated B
    int tid = threadIdx.x;
    int r0 = blockIdx.x * 256;
    int tx = tid & 15, ty = tid >> 4;
    unsigned long long acc[8][4];
#pragma unroll
    for (int i = 0; i < 8; ++i)
#pragma unroll
        for (int j = 0; j < 4; ++j) acc[i][j] = 0ull;

    for (int kk = 0; kk < IND; kk += 32) {
        // A rows may come from xu or xp (concatenated node space)
#pragma unroll
        for (int i_ = 0; i_ < 8; ++i_) {
            int f4_ = i_ * 256 + tid;
            int row_ = f4_ >> 3, kc4_ = f4_ & 7;
            int gr_ = r0 + row_;
            float4 v_ = make_float4(0.f, 0.f, 0.f, 0.f);
            if (gr_ < NU + NP) {
                const float* srcp = gr_ < NU ? xu + (size_t)gr_ * IND
                                             : xp + (size_t)(gr_ - NU) * IND;
                v_ = *(const float4*)(srcp + kk + kc4_ * 4);
            }
            As[kc4_ * 4 + 0][row_] = v_.x;
            As[kc4_ * 4 + 1][row_] = v_.y;
            As[kc4_ * 4 + 2][row_] = v_.z;
            As[kc4_ * 4 + 3][row_] = v_.w;
        }
        LOAD_BDUP(Bd, W, 64, 0, kk);
        __syncthreads();
#pragma unroll
        for (int k = 0; k < 32; ++k) FMA32(acc, As[k], Bd[k], tx, ty);
        __syncthreads();
    }
    float4 bb = *(const float4*)(b + tx * 4);
#pragma unroll
    for (int p = 0; p < 8; ++p) {
        float2 c0 = *(float2*)&acc[p][0];
        float2 c1 = *(float2*)&acc[p][1];
        float2 c2 = *(float2*)&acc[p][2];
        float2 c3 = *(float2*)&acc[p][3];
        int gr0 = r0 + ty * 16 + 2 * p;
#pragma unroll
        for (int q = 0; q < 2; ++q) {
            int gr = gr0 + q;
            if (gr >= NU + NP) continue;
            float4 o = q == 0
                ? make_float4(c0.x + bb.x, c1.x + bb.y, c2.x + bb.z, c3.x + bb.w)
                : make_float4(c0.y + bb.x, c1.y + bb.y, c2.y + bb.z, c3.y + bb.w);
            float* dst = gr < NU ? g_hu + (size_t)gr * HID
                                 : g_hp + (size_t)(gr - NU) * HID;
            *(float4*)(dst + tx * 4) = o;
        }
    }
}

// ---------------- attention scalars, H read once per node ----------------
__global__ void k_att2() {
    int part = blockIdx.y;
    __shared__ float wf[4][HID * NH];
    int nz = part ? 2 : 4;
    int zsU[4] = {0, 1, 3, 4};
    int zsP[2] = {2, 5};
#pragma unroll
    for (int zi = 0; zi < 4; ++zi) {
        if (zi < nz) {
            int z = part ? zsP[zi] : zsU[zi];
            wf[zi][threadIdx.x] = g_wf[z][threadIdx.x];
        }
    }
    __syncthreads();
    int node = blockIdx.x * 256 + threadIdx.x;
    if (node >= NU) return;
    const float* hr = (part ? g_hp : g_hu) + (size_t)node * HID;
    float acc[4][4] = {};
#pragma unroll
    for (int c = 0; c < HID; c += 4) {
        float4 h4 = *(const float4*)(hr + c);
#pragma unroll
        for (int zi = 0; zi < 4; ++zi) {
            if (zi >= nz) break;
#pragma unroll
            for (int hh = 0; hh < 4; ++hh) {
                acc[zi][hh] += h4.x * wf[zi][(c + 0) * 4 + hh]
                             + h4.y * wf[zi][(c + 1) * 4 + hh]
                             + h4.z * wf[zi][(c + 2) * 4 + hh]
                             + h4.w * wf[zi][(c + 3) * 4 + hh];
            }
        }
    }
#pragma unroll
    for (int zi = 0; zi < 4; ++zi) {
        if (zi >= nz) break;
        int z = part ? zsP[zi] : zsU[zi];
        *(float4*)&g_a[z][node * 4] =
            make_float4(acc[zi][0], acc[zi][1], acc[zi][2], acc[zi][3]);
    }
}

// ---------------- batched CSR build ----------------
__global__ void k_zero3() {
    int i = blockIdx.x * 256 + threadIdx.x;
    if (i < 3 * NU) ((int*)g_cnt3)[i] = 0;
}
__global__ void k_hist3(const int* __restrict__ d0, const int* __restrict__ d1,
                        const int* __restrict__ d2, int E) {
    int t = blockIdx.y;
    const int* dst = t == 0 ? d0 : (t == 1 ? d1 : d2);
    int e = blockIdx.x * 256 + threadIdx.x;
    if (e < E) atomicAdd(&g_cnt3[t][dst[e]], 1);
}
__global__ void __launch_bounds__(1024) k_scan_a() {
    int t = blockIdx.y, chunk = blockIdx.x;
    __shared__ int warpsum[32];
    int tid = threadIdx.x;
    int lane = tid & 31, wid = tid >> 5;
    int idx0 = chunk * SCHUNK + tid * 4;
    int v[4];
    int s = 0;
#pragma unroll
    for (int q = 0; q < 4; ++q) {
        v[q] = (idx0 + q < NU) ? g_cnt3[t][idx0 + q] : 0;
        s += v[q];
    }
    int x = s;
#pragma unroll
    for (int o = 1; o < 32; o <<= 1) {
        int y = __shfl_up_sync(0xffffffffu, x, o);
        if (lane >= o) x += y;
    }
    if (lane == 31) warpsum[wid] = x;
    __syncthreads();
    if (wid == 0) {
        int w = warpsum[lane];
#pragma unroll
        for (int o = 1; o < 32; o <<= 1) {
            int y = __shfl_up_sync(0xffffffffu, w, o);
            if (lane >= o) w += y;
        }
        warpsum[lane] = w;
    }
    __syncthreads();
    int wprev = wid ? warpsum[wid - 1] : 0;
    int excl = wprev + (x - s);
#pragma unroll
    for (int q = 0; q < 4; ++q) {
        if (idx0 + q < NU) g_rp3[t][idx0 + q] = excl;
        excl += v[q];
    }
    if (tid == 0) g_csum[t][chunk] = warpsum[31];
}
__global__ void k_scan_b() {
    int w = threadIdx.x >> 5;
    int lane = threadIdx.x & 31;
    if (w >= 3) return;
    int val = lane < NCHUNK ? g_csum[w][lane] : 0;
    int x = val;
#pragma unroll
    for (int o = 1; o < 32; o <<= 1) {
        int y = __shfl_up_sync(0xffffffffu, x, o);
        if (lane >= o) x += y;
    }
    if (lane < NCHUNK) g_coff[w][lane] = x - val;
    if (lane == 31) g_rp3[w][NU] = x;
}
__global__ void __launch_bounds__(1024) k_scan_c() {
    int t = blockIdx.y, chunk = blockIdx.x;
    int off = g_coff[t][chunk];
    int idx0 = chunk * SCHUNK + threadIdx.x * 4;
#pragma unroll
    for (int q = 0; q < 4; ++q) {
        int i = idx0 + q;
        if (i < NU) {
            int r = g_rp3[t][i] + off;
            g_rp3[t][i] = r;
            g_cur3[t][i] = r;
        }
    }
}

// ---------------- scatter src into CSR slots ----------------
__global__ void k_scat(const int* __restrict__ s0, const int* __restrict__ d0,
                       const int* __restrict__ s1, const int* __restrict__ d1,
                       const int* __restrict__ s2, const int* __restrict__ d2,
                       int E) {
    int t = blockIdx.y;
    const int* src = t == 0 ? s0 : (t == 1 ? s1 : s2);
    const int* dst = t == 0 ? d0 : (t == 1 ? d1 : d2);
    int e = blockIdx.x * 256 + threadIdx.x;
    if (e >= E) return;
    int p = atomicAdd(&g_cur3[t][dst[e]], 1);
    g_psrc[t][p] = src[e];
}

// ---------------- warp-per-dst: logits + softmax + HID-space aggregation ----------------
__global__ void __launch_bounds__(256) k_gat4() {
    int t = blockIdx.y;
    int d = (blockIdx.x * 256 + threadIdx.x) >> 5;
    int lane = threadIdx.x & 31;
    if (d >= NU) return;
    int beg = g_rp3[t][d], end = g_rp3[t][d + 1];
    int deg = end - beg;
    const float* hsrc = (t == 1) ? g_hp : g_hu;
    const int* psrc = g_psrc[t];
    const float* aS = g_a[2 * t];
    float4 ad = *(const float4*)&g_a[2 * t + 1][d * 4];
    int c0 = lane * 2;
    float* zp = &g_z[t][(size_t)d * HH];

    if (deg == 0) {
#pragma unroll
        for (int h = 0; h < 4; ++h)
            *(float2*)&zp[h * HID + c0] = make_float2(0.f, 0.f);
        return;
    }

    float acc[4][2] = {};

    if (deg <= 32) {
        bool valid = lane < deg;
        int sj = valid ? psrc[beg + lane] : 0;
        float4 ev = make_float4(-INFINITY, -INFINITY, -INFINITY, -INFINITY);
        if (valid) {
            float4 s4 = *(const float4*)&aS[sj * 4];
            ev = make_float4(lrelu(s4.x + ad.x), lrelu(s4.y + ad.y),
                             lrelu(s4.z + ad.z), lrelu(s4.w + ad.w));
        }
        float m0 = ev.x, m1 = ev.y, m2 = ev.z, m3 = ev.w;
#pragma unroll
        for (int o = 16; o; o >>= 1) {
            m0 = fmaxf(m0, __shfl_xor_sync(0xffffffffu, m0, o));
            m1 = fmaxf(m1, __shfl_xor_sync(0xffffffffu, m1, o));
            m2 = fmaxf(m2, __shfl_xor_sync(0xffffffffu, m2, o));
            m3 = fmaxf(m3, __shfl_xor_sync(0xffffffffu, m3, o));
        }
        float e0 = valid ? __expf(ev.x - m0) : 0.f;
        float e1 = valid ? __expf(ev.y - m1) : 0.f;
        float e2 = valid ? __expf(ev.z - m2) : 0.f;
        float e3 = valid ? __expf(ev.w - m3) : 0.f;
        float s0 = e0, s1 = e1, s2 = e2, s3 = e3;
#pragma unroll
        for (int o = 16; o; o >>= 1) {
            s0 += __shfl_xor_sync(0xffffffffu, s0, o);
            s1 += __shfl_xor_sync(0xffffffffu, s1, o);
            s2 += __shfl_xor_sync(0xffffffffu, s2, o);
            s3 += __shfl_xor_sync(0xffffffffu, s3, o);
        }
        float ax = e0 / (s0 + 1e-16f);
        float ay = e1 / (s1 + 1e-16f);
        float az = e2 / (s2 + 1e-16f);
        float aw = e3 / (s3 + 1e-16f);
        for (int k = 0; k < deg; ++k) {
            int sr  = __shfl_sync(0xffffffffu, sj, k);
            float bx = __shfl_sync(0xffffffffu, ax, k);
            float by = __shfl_sync(0xffffffffu, ay, k);
            float bz = __shfl_sync(0xffffffffu, az, k);
            float bw = __shfl_sync(0xffffffffu, aw, k);
            float2 v = *(const float2*)&hsrc[(size_t)sr * HID + c0];
            acc[0][0] += bx * v.x; acc[0][1] += bx * v.y;
            acc[1][0] += by * v.x; acc[1][1] += by * v.y;
            acc[2][0] += bz * v.x; acc[2][1] += bz * v.y;
            acc[3][0] += bw * v.x; acc[3][1] += bw * v.y;
        }
    } else {
        float m0 = -INFINITY, m1 = -INFINITY, m2 = -INFINITY, m3 = -INFINITY;
        for (int j = beg + lane; j < end; j += 32) {
            float4 s4 = *(const float4*)&aS[psrc[j] * 4];
            m0 = fmaxf(m0, lrelu(s4.x + ad.x));
            m1 = fmaxf(m1, lrelu(s4.y + ad.y));
            m2 = fmaxf(m2, lrelu(s4.z + ad.z));
            m3 = fmaxf(m3, lrelu(s4.w + ad.w));
        }
#pragma unroll
        for (int o = 16; o; o >>= 1) {
            m0 = fmaxf(m0, __shfl_xor_sync(0xffffffffu, m0, o));
            m1 = fmaxf(m1, __shfl_xor_sync(0xffffffffu, m1, o));
            m2 = fmaxf(m2, __shfl_xor_sync(0xffffffffu, m2, o));
            m3 = fmaxf(m3, __shfl_xor_sync(0xffffffffu, m3, o));
        }
        float s0 = 0.f, s1 = 0.f, s2 = 0.f, s3 = 0.f;
        for (int j = beg + lane; j < end; j += 32) {
            float4 s4 = *(const float4*)&aS[psrc[j] * 4];
            s0 += __expf(lrelu(s4.x + ad.x) - m0);
            s1 += __expf(lrelu(s4.y + ad.y) - m1);
            s2 += __expf(lrelu(s4.z + ad.z) - m2);
            s3 += __expf(lrelu(s4.w + ad.w) - m3);
        }
#pragma unroll
        for (int o = 16; o; o >>= 1) {
            s0 += __shfl_xor_sync(0xffffffffu, s0, o);
            s1 += __shfl_xor_sync(0xffffffffu, s1, o);
            s2 += __shfl_xor_sync(0xffffffffu, s2, o);
            s3 += __shfl_xor_sync(0xffffffffu, s3, o);
        }
        float i0 = 1.f / (s0 + 1e-16f), i1 = 1.f / (s1 + 1e-16f);
        float i2 = 1.f / (s2 + 1e-16f), i3 = 1.f / (s3 + 1e-16f);
        for (int base = beg; base < end; base += 32) {
            int j = base + lane;
            float ax = 0.f, ay = 0.f, az = 0.f, aw = 0.f;
            int sj = 0;
            if (j < end) {
                sj = psrc[j];
                float4 s4 = *(const float4*)&aS[sj * 4];
                ax = __expf(lrelu(s4.x + ad.x) - m0) * i0;
                ay = __expf(lrelu(s4.y + ad.y) - m1) * i1;
                az = __expf(lrelu(s4.z + ad.z) - m2) * i2;
                aw = __expf(lrelu(s4.w + ad.w) - m3) * i3;
            }
            int cnt = min(32, end - base);
            for (int k = 0; k < cnt; ++k) {
                int sr  = __shfl_sync(0xffffffffu, sj, k);
                float bx = __shfl_sync(0xffffffffu, ax, k);
                float by = __shfl_sync(0xffffffffu, ay, k);
                float bz = __shfl_sync(0xffffffffu, az, k);
                float bw = __shfl_sync(0xffffffffu, aw, k);
                float2 v = *(const float2*)&hsrc[(size_t)sr * HID + c0];
                acc[0][0] += bx * v.x; acc[0][1] += bx * v.y;
                acc[1][0] += by * v.x; acc[1][1] += by * v.y;
                acc[2][0] += bz * v.x; acc[2][1] += bz * v.y;
                acc[3][0] += bw * v.x; acc[3][1] += bw * v.y;
            }
        }
    }
#pragma unroll
    for (int hh = 0; hh < 4; ++hh)
        *(float2*)&zp[hh * HID + c0] = make_float2(acc[hh][0], acc[hh][1]);
}

// ---------------- fused per-head GEMM + bias + ELU ----------------
// zi=0 (user):  elu(z0@lin0 + z1@lin1 + b_u2u + b_p2u) -> g_outU
// zi=1 (post):  elu(z2@lin2 + b_u2p)                   -> dout post region
__global__ void __launch_bounds__(256, 2) k_hg2(const float* __restrict__ l0,
                                                const float* __restrict__ l1,
                                                const float* __restrict__ l2,
                                                const float* __restrict__ b0,
                                                const float* __restrict__ b1,
                                                const float* __restrict__ b2,
                                                float* __restrict__ dout) {
    __shared__ float As[32][264];
    __shared__ float Bd[32][136];
    int zi = blockIdx.z, h = blockIdx.y;
    int tid = threadIdx.x;
    int r0 = blockIdx.x * 256;
    int tx = tid & 15, ty = tid >> 4;

    unsigned long long acc[8][4];
#pragma unroll
    for (int i = 0; i < 8; ++i)
#pragma unroll
        for (int j = 0; j < 4; ++j) acc[i][j] = 0ull;

    int ntt = zi == 0 ? 2 : 1;
    for (int tt = 0; tt < ntt; ++tt) {
        int t = zi == 0 ? tt : 2;
        const float* A = g_z[t];
        const float* lin = t == 0 ? l0 : (t == 1 ? l1 : l2);
        for (int kk = 0; kk < HID; kk += 32) {
            LOAD_A256(As, A, HH, h * HID, r0, kk, NU);
            LOAD_BDUP(Bd, lin, HH, h * HID, kk);
            __syncthreads();
#pragma unroll
            for (int k = 0; k < 32; ++k) FMA32(acc, As[k], Bd[k], tx, ty);
            __syncthreads();
        }
    }
    float4 bb;
    if (zi == 0) {
        float4 x1 = *(const float4*)(b0 + h * HID + tx * 4);
        float4 x2 = *(const float4*)(b1 + h * HID + tx * 4);
        bb = make_float4(x1.x + x2.x, x1.y + x2.y, x1.z + x2.z, x1.w + x2.w);
    } else {
        bb = *(const float4*)(b2 + h * HID + tx * 4);
    }
#pragma unroll
    for (int p = 0; p < 8; ++p) {
        float2 c0 = *(float2*)&acc[p][0];
        float2 c1 = *(float2*)&acc[p][1];
        float2 c2 = *(float2*)&acc[p][2];
        float2 c3 = *(float2*)&acc[p][3];
        int gr0 = r0 + ty * 16 + 2 * p;
#pragma unroll
        for (int q = 0; q < 2; ++q) {
            int gr = gr0 + q;
            if (gr >= NU) continue;
            float4 o = q == 0
                ? make_float4(elu(c0.x + bb.x), elu(c1.x + bb.y),
                              elu(c2.x + bb.z), elu(c3.x + bb.w))
                : make_float4(elu(c0.y + bb.x), elu(c1.y + bb.y),
                              elu(c2.y + bb.z), elu(c3.y + bb.w));
            if (zi == 0)
                *(float4*)&g_outU[(size_t)gr * HH + h * HID + tx * 4] = o;
            else
                *(float4*)(dout + (size_t)NU * OUTD + (size_t)gr * HH + h * HID + tx * 4) = o;
        }
    }
}

// ---------------- user output: g_outU @ W_out + b_out ----------------
__global__ void __launch_bounds__(256, 2) k_gout(const float* __restrict__ W,
                                                 const float* __restrict__ bo,
                                                 float* __restrict__ dout) {
    __shared__ float As[32][264];
    __shared__ float Bd[32][136];
    int tid = threadIdx.x;
    int r0 = blockIdx.x * 256;
    int tx = tid & 15, ty = tid >> 4;
    unsigned long long acc[8][4];
#pragma unroll
    for (int i = 0; i < 8; ++i)
#pragma unroll
        for (int j = 0; j < 4; ++j) acc[i][j] = 0ull;

    for (int kk = 0; kk < HH; kk += 32) {
        LOAD_A256(As, g_outU, HH, 0, r0, kk, NU);
        LOAD_BDUP(Bd, W, OUTD, 0, kk);
        __syncthreads();
#pragma unroll
        for (int k = 0; k < 32; ++k) FMA32(acc, As[k], Bd[k], tx, ty);
        __syncthreads();
    }
    float4 bb = *(const float4*)(bo + tx * 4);
#pragma unroll
    for (int p = 0; p < 8; ++p) {
        float2 c0 = *(float2*)&acc[p][0];
        float2 c1 = *(float2*)&acc[p][1];
        float2 c2 = *(float2*)&acc[p][2];
        float2 c3 = *(float2*)&acc[p][3];
        int gr0 = r0 + ty * 16 + 2 * p;
#pragma unroll
        for (int q = 0; q < 2; ++q) {
            int gr = gr0 + q;
            if (gr >= NU) continue;
            float4 o = q == 0
                ? make_float4(c0.x + bb.x, c1.x + bb.y, c2.x + bb.z, c3.x + bb.w)
                : make_float4(c0.y + bb.x, c1.y + bb.y, c2.y + bb.z, c3.y + bb.w);
            *(float4*)(dout + (size_t)gr * OUTD + tx * 4) = o;
        }
    }
}

// ---------------- launch ----------------
extern "C" void kernel_launch(void* const* d_in, const int* in_sizes, int n_in,
                              void* d_out, int out_size) {
    const float* x_user     = (const float*)d_in[0];
    const float* x_post     = (const float*)d_in[1];
    const int*   src_u2u    = (const int*)d_in[2];
    const int*   dst_u2u    = (const int*)d_in[3];
    const int*   src_p2u    = (const int*)d_in[4];
    const int*   dst_p2u    = (const int*)d_in[5];
    const int*   src_u2p    = (const int*)d_in[6];
    const int*   dst_u2p    = (const int*)d_in[7];
    const float* W_proj     = (const float*)d_in[8];
    const float* b_proj     = (const float*)d_in[9];
    const float* lin_u2u    = (const float*)d_in[10];
    const float* att_s_u2u  = (const float*)d_in[11];
    const float* att_d_u2u  = (const float*)d_in[12];
    const float* bias_u2u   = (const float*)d_in[13];
    const float* lin_p2u    = (const float*)d_in[14];
    const float* att_s_p2u  = (const float*)d_in[15];
    const float* att_d_p2u  = (const float*)d_in[16];
    const float* bias_p2u   = (const float*)d_in[17];
    const float* lin_u2p    = (const float*)d_in[18];
    const float* att_s_u2p  = (const float*)d_in[19];
    const float* att_d_u2p  = (const float*)d_in[20];
    const float* bias_u2p   = (const float*)d_in[21];
    const float* W_out      = (const float*)d_in[22];
    const float* b_out      = (const float*)d_in[23];
    float* out = (float*)d_out;
    int E = in_sizes[2];
    int gE = (E + 255) / 256;

    // ncu -s 5 lands on stream launch index 3 -> keep k_proj there
    k_fold<<<6, 256>>>(lin_u2u, lin_p2u, lin_u2p,                           // 0
                       att_s_u2u, att_d_u2u, att_s_p2u, att_d_p2u, att_s_u2p, att_d_u2p);
    k_zero3<<<(3 * NU + 255) / 256, 256>>>();                               // 1
    k_hist3<<<dim3(gE, 3), 256>>>(dst_u2u, dst_p2u, dst_u2p, E);            // 2
    k_proj<<<(NU + NP + 255) / 256, 256>>>(x_user, x_post, W_proj, b_proj); // 3 (profiled)
    k_scan_a<<<dim3(NCHUNK, 3), 1024>>>();                                  // 4
    k_scan_b<<<1, 96>>>();                                                  // 5
    k_scan_c<<<dim3(NCHUNK, 3), 1024>>>();                                  // 6
    k_att2<<<dim3((NU + 255) / 256, 2), 256>>>();                           // 7
    k_scat<<<dim3(gE, 3), 256>>>(src_u2u, dst_u2u, src_p2u, dst_p2u,        // 8
                                 src_u2p, dst_u2p, E);
    k_gat4<<<dim3((NU * 32 + 255) / 256, 3), 256>>>();                      // 9
    k_hg2<<<dim3((NU + 255) / 256, NH, 2), 256>>>(lin_u2u, lin_p2u, lin_u2p, // 10
                                                  bias_u2u, bias_p2u, bias_u2p, out);
    k_gout<<<(NU + 255) / 256, 256>>>(W_out, b_out, out);                   // 11
}